// round 6
// baseline (speedup 1.0000x reference)
#include <cuda_runtime.h>

// Max pool 2x2 stride 2, NCHW (32,128,224,224) fp32 -> (32,128,112,112)
// HBM-bound streaming: 822MB read + 206MB write (mandatory, zero reuse).
// Measured ceiling across shapes: ~90% DRAM active / ~7.15 TB/s.
//
// R6: R4 shape (2 quads/thread, 256 threads, die-after-work grid, MLP_p1=8)
// + 32-bit byte-offset addressing (input 822MB < 2GB): shorter ALU path from
// block start to first LDG, less IMAD.WIDE pressure.

#define IW   224
#define IH   224
#define OW   112
#define OH   112
#define OW4  28                       // float4 quads per output row
#define NC   (32 * 128)
#define TOTAL_QUADS (NC * OH * OW4)   // 12,845,056 = 512 * 25088

// byte offset of quad p's first input float4 (fits in uint32: < 822MB)
__device__ __forceinline__ unsigned decode_off(int p) {
    const int ow4 = p % OW4;
    const int t1  = p / OW4;
    const int oh  = t1 % OH;
    const int nc  = t1 / OH;
    return ((unsigned)nc * (IH * IW) + (unsigned)(2 * oh) * IW + 8u * (unsigned)ow4) * 4u;
}

__device__ __forceinline__ float4 fmax4(float4 t0, float4 t1, float4 u0, float4 u1) {
    float4 r;
    r.x = fmaxf(fmaxf(t0.x, t0.y), fmaxf(u0.x, u0.y));
    r.y = fmaxf(fmaxf(t0.z, t0.w), fmaxf(u0.z, u0.w));
    r.z = fmaxf(fmaxf(t1.x, t1.y), fmaxf(u1.x, u1.y));
    r.w = fmaxf(fmaxf(t1.z, t1.w), fmaxf(u1.z, u1.w));
    return r;
}

__global__ __launch_bounds__(256, 8)
void pool2d_kernel(const char* __restrict__ in_b, float4* __restrict__ out) {
    // block covers 512 consecutive quads; thread t does quads t and t+256
    const int pA = blockIdx.x * 512 + threadIdx.x;
    const int pB = pA + 256;

    const unsigned offA = decode_off(pA);
    const unsigned offB = decode_off(pB);

    const float4* a_r0 = reinterpret_cast<const float4*>(in_b + offA);
    const float4* a_r1 = reinterpret_cast<const float4*>(in_b + offA + IW * 4);
    const float4* b_r0 = reinterpret_cast<const float4*>(in_b + offB);
    const float4* b_r1 = reinterpret_cast<const float4*>(in_b + offB + IW * 4);

    // 8 independent loads, front-batched
    const float4 a00 = __ldcs(a_r0);  const float4 a01 = __ldcs(a_r0 + 1);
    const float4 a10 = __ldcs(a_r1);  const float4 a11 = __ldcs(a_r1 + 1);
    const float4 b00 = __ldcs(b_r0);  const float4 b01 = __ldcs(b_r0 + 1);
    const float4 b10 = __ldcs(b_r1);  const float4 b11 = __ldcs(b_r1 + 1);

    const float4 rA = fmax4(a00, a01, a10, a11);
    const float4 rB = fmax4(b00, b01, b10, b11);

    __stcs(out + pA, rA);
    __stcs(out + pB, rB);
}

extern "C" void kernel_launch(void* const* d_in, const int* in_sizes, int n_in,
                              void* d_out, int out_size) {
    const char* x = (const char*)d_in[0];
    float4* out = (float4*)d_out;

    const int blocks  = TOTAL_QUADS / 512;   // 25088, no tail
    const int threads = 256;

    pool2d_kernel<<<blocks, threads>>>(x, out);
}